// round 1
// baseline (speedup 1.0000x reference)
#include <cuda_runtime.h>
#include <math.h>

#define N    2708
#define INC  1433
#define OC   128
#define NCH  32
#define RC   85    // ceil(N/NCH)
#define RPB  16
#define JT   64

// ---------------- scratch (static device memory, no runtime alloc) ----------
__device__ float g_K[N * OC];
__device__ float g_k1[N], g_k2[N];
__device__ float g_part1[NCH * N], g_part2[NCH * N];
__device__ float g_s1[N], g_s2[N];
__device__ float g_p[N], g_q[N];
__device__ float g_m[N], g_linv[N];

// ---------------- K = X @ W^T  (BM=32, BN=64, BK=32, 256 thr) ---------------
__global__ void gemm_k(const float* __restrict__ X, const float* __restrict__ W) {
    const int BM = 32, BN = 64, BK = 32;
    __shared__ float Xs[BM][BK + 1];
    __shared__ float Ws[BN][BK + 1];
    int i0 = blockIdx.y * BM;
    int c0 = blockIdx.x * BN;
    int t  = threadIdx.x;
    int tr = t >> 4;   // 0..15 -> rows 2*tr, 2*tr+1
    int tc = t & 15;   // 0..15 -> cols 4*tc..4*tc+3
    float acc[2][4] = {};
    for (int kt = 0; kt < INC; kt += BK) {
#pragma unroll
        for (int l = 0; l < 4; l++) {
            int e = t + l * 256;
            int r = e >> 5, kk = e & 31;
            int gi = i0 + r, gk = kt + kk;
            Xs[r][kk] = (gi < N && gk < INC) ? X[gi * INC + gk] : 0.f;
        }
#pragma unroll
        for (int l = 0; l < 8; l++) {
            int e = t + l * 256;
            int c = e >> 5, kk = e & 31;
            int gk = kt + kk;
            Ws[c][kk] = (gk < INC) ? W[(c0 + c) * INC + gk] : 0.f;
        }
        __syncthreads();
#pragma unroll
        for (int kk = 0; kk < BK; kk++) {
            float a0 = Xs[2 * tr][kk], a1 = Xs[2 * tr + 1][kk];
#pragma unroll
            for (int j = 0; j < 4; j++) {
                float b = Ws[4 * tc + j][kk];
                acc[0][j] += a0 * b;
                acc[1][j] += a1 * b;
            }
        }
        __syncthreads();
    }
#pragma unroll
    for (int r = 0; r < 2; r++) {
        int gi = i0 + 2 * tr + r;
        if (gi < N) {
#pragma unroll
            for (int j = 0; j < 4; j++)
                g_K[gi * OC + c0 + 4 * tc + j] = acc[r][j];
        }
    }
}

// ---------------- k1 = K a1^T, k2 = K a2^T (one warp per row) ---------------
__global__ void k1k2_kernel(const float* __restrict__ a1, const float* __restrict__ a2) {
    int w = threadIdx.x >> 5;
    int lane = threadIdx.x & 31;
    int i = blockIdx.x * 8 + w;
    if (i >= N) return;
    float d1 = 0.f, d2 = 0.f;
#pragma unroll
    for (int u = 0; u < 4; u++) {
        int c = lane + 32 * u;
        float kv = g_K[i * OC + c];
        d1 += kv * a1[c];
        d2 += kv * a2[c];
    }
#pragma unroll
    for (int off = 16; off; off >>= 1) {
        d1 += __shfl_down_sync(0xffffffffu, d1, off);
        d2 += __shfl_down_sync(0xffffffffu, d2, off);
    }
    if (lane == 0) { g_k1[i] = d1; g_k2[i] = d2; }
}

// ---------------- column reductions: t1 = U^T k1, t2 = U^T 1 (partials) -----
__global__ void colpart(const float* __restrict__ U) {
    int j  = blockIdx.x * 256 + threadIdx.x;
    int ch = blockIdx.y;
    if (j >= N) return;
    int ib = ch * RC;
    int ie = min(N, ib + RC);
    float a = 0.f, b = 0.f;
    for (int i = ib; i < ie; i++) {
        float u = U[i * N + j];
        a += u * g_k1[i];
        b += u;
    }
    g_part1[ch * N + j] = a;
    g_part2[ch * N + j] = b;
}

// ---------------- s = lmbd * t  (fixed-order chunk reduce) ------------------
__global__ void colreduce(const float* __restrict__ lmbd) {
    int j = blockIdx.x * 256 + threadIdx.x;
    if (j >= N) return;
    float a = 0.f, b = 0.f;
#pragma unroll
    for (int c = 0; c < NCH; c++) {
        a += g_part1[c * N + j];
        b += g_part2[c * N + j];
    }
    float l = lmbd[j];
    g_s1[j] = l * a;
    g_s2[j] = l * b;
}

// ---------------- p = U s1, q = U s2 (one block per row) --------------------
__global__ void pq_kernel(const float* __restrict__ U) {
    __shared__ float r1[256], r2[256];
    int i = blockIdx.x;
    int t = threadIdx.x;
    float a = 0.f, b = 0.f;
    for (int j = t; j < N; j += 256) {
        float u = U[i * N + j];
        a += u * g_s1[j];
        b += u * g_s2[j];
    }
    r1[t] = a; r2[t] = b;
    __syncthreads();
    for (int s = 128; s; s >>= 1) {
        if (t < s) { r1[t] += r1[t + s]; r2[t] += r2[t + s]; }
        __syncthreads();
    }
    if (t == 0) { g_p[i] = r1[0]; g_q[i] = r2[0]; }
}

// ---------------- per-row masked softmax stats: m_i, 1/l_i ------------------
__global__ void stats_kernel(const int* __restrict__ A) {
    __shared__ float red[256];
    int i = blockIdx.x, t = threadIdx.x;
    float pi = g_p[i], qi = g_q[i];
    const int* Arow = A + (size_t)i * N;
    float mx = -INFINITY;
    for (int j = t; j < N; j += 256)
        if (Arow[j]) mx = fmaxf(mx, fabsf(pi + qi * g_k2[j]));
    red[t] = mx;
    __syncthreads();
    for (int s = 128; s; s >>= 1) {
        if (t < s) red[t] = fmaxf(red[t], red[t + s]);
        __syncthreads();
    }
    float m = red[0];
    __syncthreads();
    float sum = 0.f;
    for (int j = t; j < N; j += 256)
        if (Arow[j]) sum += __expf(fabsf(pi + qi * g_k2[j]) - m);
    red[t] = sum;
    __syncthreads();
    for (int s = 128; s; s >>= 1) {
        if (t < s) red[t] += red[t + s];
        __syncthreads();
    }
    if (t == 0) { g_m[i] = m; g_linv[i] = 1.f / red[0]; }
}

// ---------------- H = alpha @ K, fused (16 rows/block, K staged in smem) ----
__global__ void attn_h(const int* __restrict__ A, float* __restrict__ H) {
    __shared__ float4 Ksh[JT * 32];            // 64 j-rows x 128 cols = 32KB
    __shared__ float  wsh[RPB * JT];           // 16 rows x 64 j        = 4KB
    __shared__ float  pm[RPB], qm[RPB], mm[RPB], lm[RPB];
    int i0 = blockIdx.x * RPB;
    int t  = threadIdx.x;
    if (t < RPB) {
        int gi = i0 + t;
        if (gi < N) { pm[t] = g_p[gi]; qm[t] = g_q[gi]; mm[t] = g_m[gi]; lm[t] = g_linv[gi]; }
        else        { pm[t] = 0.f; qm[t] = 0.f; mm[t] = 0.f; lm[t] = 0.f; }
    }
    int cg = t & 31;   // cols 4*cg..4*cg+3 (float4)
    int rg = t >> 5;   // rows 2*rg, 2*rg+1
    float4 acc0 = make_float4(0.f, 0.f, 0.f, 0.f);
    float4 acc1 = make_float4(0.f, 0.f, 0.f, 0.f);
    __syncthreads();
    for (int j0 = 0; j0 < N; j0 += JT) {
        // stage K tile (coalesced float4)
#pragma unroll
        for (int l = 0; l < 8; l++) {
            int e  = t + l * 256;            // float4 index 0..2047
            int jj = e >> 5, c4 = e & 31;
            int gj = j0 + jj;
            Ksh[jj * 32 + c4] = (gj < N) ? ((const float4*)g_K)[gj * 32 + c4]
                                         : make_float4(0.f, 0.f, 0.f, 0.f);
        }
        // attention weights for this tile
#pragma unroll
        for (int l = 0; l < 4; l++) {
            int e  = t + l * 256;            // 0..1023
            int r  = e >> 6, jj = e & 63;
            int gi = i0 + r, gj = j0 + jj;
            float w = 0.f;
            if (gi < N && gj < N && A[(size_t)gi * N + gj])
                w = __expf(fabsf(pm[r] + qm[r] * g_k2[gj]) - mm[r]) * lm[r];
            wsh[r * JT + jj] = w;
        }
        __syncthreads();
#pragma unroll 4
        for (int jj = 0; jj < JT; jj++) {
            float4 kv = Ksh[jj * 32 + cg];
            float w0 = wsh[(rg * 2) * JT + jj];
            float w1 = wsh[(rg * 2 + 1) * JT + jj];
            acc0.x += w0 * kv.x; acc0.y += w0 * kv.y; acc0.z += w0 * kv.z; acc0.w += w0 * kv.w;
            acc1.x += w1 * kv.x; acc1.y += w1 * kv.y; acc1.z += w1 * kv.z; acc1.w += w1 * kv.w;
        }
        __syncthreads();
    }
    int r0 = i0 + rg * 2;
    if (r0 < N)     ((float4*)H)[(size_t)r0 * 32 + cg]       = acc0;
    if (r0 + 1 < N) ((float4*)H)[(size_t)(r0 + 1) * 32 + cg] = acc1;
}

// ---------------- launch ----------------------------------------------------
extern "C" void kernel_launch(void* const* d_in, const int* in_sizes, int n_in,
                              void* d_out, int out_size) {
    (void)in_sizes; (void)n_in; (void)out_size;
    const float* X    = (const float*)d_in[0];
    const int*   A    = (const int*)d_in[1];
    const float* U    = (const float*)d_in[2];
    const float* W    = (const float*)d_in[3];
    const float* a1   = (const float*)d_in[4];
    const float* a2   = (const float*)d_in[5];
    const float* lmbd = (const float*)d_in[6];
    float* H = (float*)d_out;

    gemm_k   <<<dim3(2, (N + 31) / 32), 256>>>(X, W);
    k1k2_kernel<<<(N + 7) / 8, 256>>>(a1, a2);
    colpart  <<<dim3((N + 255) / 256, NCH), 256>>>(U);
    colreduce<<<(N + 255) / 256, 256>>>(lmbd);
    pq_kernel<<<N, 256>>>(U);
    stats_kernel<<<N, 256>>>(A);
    attn_h   <<<(N + RPB - 1) / RPB, 256>>>(A, H);
}

// round 2
// speedup vs baseline: 1.0006x; 1.0006x over previous
#include <cuda_runtime.h>
#include <math.h>

#define N    2708
#define INC  1433
#define OC   128
#define NCH  32
#define RC   85    // ceil(N/NCH)
#define RPB  16
#define JT   64

// ---------------- scratch (static device memory, no runtime alloc) ----------
__device__ float g_K[N * OC];
__device__ float g_k1[N], g_k2[N];
__device__ float g_part1[NCH * N], g_part2[NCH * N];
__device__ float g_s1[N], g_s2[N];
__device__ float g_p[N], g_q[N];
__device__ float g_m[N], g_linv[N];

// ---------------- K = X @ W^T  (BM=32, BN=64, BK=32, 256 thr) ---------------
__global__ void gemm_k(const float* __restrict__ X, const float* __restrict__ W) {
    const int BM = 32, BN = 64, BK = 32;
    __shared__ float Xs[BM][BK + 1];
    __shared__ float Ws[BN][BK + 1];
    int i0 = blockIdx.y * BM;
    int c0 = blockIdx.x * BN;
    int t  = threadIdx.x;
    int tr = t >> 4;   // 0..15 -> rows 2*tr, 2*tr+1
    int tc = t & 15;   // 0..15 -> cols 4*tc..4*tc+3
    float acc[2][4] = {};
    for (int kt = 0; kt < INC; kt += BK) {
#pragma unroll
        for (int l = 0; l < 4; l++) {
            int e = t + l * 256;
            int r = e >> 5, kk = e & 31;
            int gi = i0 + r, gk = kt + kk;
            Xs[r][kk] = (gi < N && gk < INC) ? X[gi * INC + gk] : 0.f;
        }
#pragma unroll
        for (int l = 0; l < 8; l++) {
            int e = t + l * 256;
            int c = e >> 5, kk = e & 31;
            int gk = kt + kk;
            Ws[c][kk] = (gk < INC) ? W[(c0 + c) * INC + gk] : 0.f;
        }
        __syncthreads();
#pragma unroll
        for (int kk = 0; kk < BK; kk++) {
            float a0 = Xs[2 * tr][kk], a1 = Xs[2 * tr + 1][kk];
#pragma unroll
            for (int j = 0; j < 4; j++) {
                float b = Ws[4 * tc + j][kk];
                acc[0][j] += a0 * b;
                acc[1][j] += a1 * b;
            }
        }
        __syncthreads();
    }
#pragma unroll
    for (int r = 0; r < 2; r++) {
        int gi = i0 + 2 * tr + r;
        if (gi < N) {
#pragma unroll
            for (int j = 0; j < 4; j++)
                g_K[gi * OC + c0 + 4 * tc + j] = acc[r][j];
        }
    }
}

// ---------------- k1 = K a1^T, k2 = K a2^T (one warp per row) ---------------
__global__ void k1k2_kernel(const float* __restrict__ a1, const float* __restrict__ a2) {
    int w = threadIdx.x >> 5;
    int lane = threadIdx.x & 31;
    int i = blockIdx.x * 8 + w;
    if (i >= N) return;
    float d1 = 0.f, d2 = 0.f;
#pragma unroll
    for (int u = 0; u < 4; u++) {
        int c = lane + 32 * u;
        float kv = g_K[i * OC + c];
        d1 += kv * a1[c];
        d2 += kv * a2[c];
    }
#pragma unroll
    for (int off = 16; off; off >>= 1) {
        d1 += __shfl_down_sync(0xffffffffu, d1, off);
        d2 += __shfl_down_sync(0xffffffffu, d2, off);
    }
    if (lane == 0) { g_k1[i] = d1; g_k2[i] = d2; }
}

// ---------------- column reductions: t1 = U^T k1, t2 = U^T 1 (partials) -----
__global__ void colpart(const float* __restrict__ U) {
    int j  = blockIdx.x * 256 + threadIdx.x;
    int ch = blockIdx.y;
    if (j >= N) return;
    int ib = ch * RC;
    int ie = min(N, ib + RC);
    float a = 0.f, b = 0.f;
    for (int i = ib; i < ie; i++) {
        float u = U[i * N + j];
        a += u * g_k1[i];
        b += u;
    }
    g_part1[ch * N + j] = a;
    g_part2[ch * N + j] = b;
}

// ---------------- s = lmbd * t  (fixed-order chunk reduce) ------------------
__global__ void colreduce(const float* __restrict__ lmbd) {
    int j = blockIdx.x * 256 + threadIdx.x;
    if (j >= N) return;
    float a = 0.f, b = 0.f;
#pragma unroll
    for (int c = 0; c < NCH; c++) {
        a += g_part1[c * N + j];
        b += g_part2[c * N + j];
    }
    float l = lmbd[j];
    g_s1[j] = l * a;
    g_s2[j] = l * b;
}

// ---------------- p = U s1, q = U s2 (one block per row) --------------------
__global__ void pq_kernel(const float* __restrict__ U) {
    __shared__ float r1[256], r2[256];
    int i = blockIdx.x;
    int t = threadIdx.x;
    float a = 0.f, b = 0.f;
    for (int j = t; j < N; j += 256) {
        float u = U[i * N + j];
        a += u * g_s1[j];
        b += u * g_s2[j];
    }
    r1[t] = a; r2[t] = b;
    __syncthreads();
    for (int s = 128; s; s >>= 1) {
        if (t < s) { r1[t] += r1[t + s]; r2[t] += r2[t + s]; }
        __syncthreads();
    }
    if (t == 0) { g_p[i] = r1[0]; g_q[i] = r2[0]; }
}

// ---------------- per-row masked softmax stats: m_i, 1/l_i ------------------
__global__ void stats_kernel(const int* __restrict__ A) {
    __shared__ float red[256];
    int i = blockIdx.x, t = threadIdx.x;
    float pi = g_p[i], qi = g_q[i];
    const int* Arow = A + (size_t)i * N;
    float mx = -INFINITY;
    for (int j = t; j < N; j += 256)
        if (Arow[j]) mx = fmaxf(mx, fabsf(pi + qi * g_k2[j]));
    red[t] = mx;
    __syncthreads();
    for (int s = 128; s; s >>= 1) {
        if (t < s) red[t] = fmaxf(red[t], red[t + s]);
        __syncthreads();
    }
    float m = red[0];
    __syncthreads();
    float sum = 0.f;
    for (int j = t; j < N; j += 256)
        if (Arow[j]) sum += __expf(fabsf(pi + qi * g_k2[j]) - m);
    red[t] = sum;
    __syncthreads();
    for (int s = 128; s; s >>= 1) {
        if (t < s) red[t] += red[t + s];
        __syncthreads();
    }
    if (t == 0) { g_m[i] = m; g_linv[i] = 1.f / red[0]; }
}

// ---------------- H = alpha @ K, fused (16 rows/block, K staged in smem) ----
__global__ void attn_h(const int* __restrict__ A, float* __restrict__ H) {
    __shared__ float4 Ksh[JT * 32];            // 64 j-rows x 128 cols = 32KB
    __shared__ float  wsh[RPB * JT];           // 16 rows x 64 j        = 4KB
    __shared__ float  pm[RPB], qm[RPB], mm[RPB], lm[RPB];
    int i0 = blockIdx.x * RPB;
    int t  = threadIdx.x;
    if (t < RPB) {
        int gi = i0 + t;
        if (gi < N) { pm[t] = g_p[gi]; qm[t] = g_q[gi]; mm[t] = g_m[gi]; lm[t] = g_linv[gi]; }
        else        { pm[t] = 0.f; qm[t] = 0.f; mm[t] = 0.f; lm[t] = 0.f; }
    }
    int cg = t & 31;   // cols 4*cg..4*cg+3 (float4)
    int rg = t >> 5;   // rows 2*rg, 2*rg+1
    float4 acc0 = make_float4(0.f, 0.f, 0.f, 0.f);
    float4 acc1 = make_float4(0.f, 0.f, 0.f, 0.f);
    __syncthreads();
    for (int j0 = 0; j0 < N; j0 += JT) {
        // stage K tile (coalesced float4)
#pragma unroll
        for (int l = 0; l < 8; l++) {
            int e  = t + l * 256;            // float4 index 0..2047
            int jj = e >> 5, c4 = e & 31;
            int gj = j0 + jj;
            Ksh[jj * 32 + c4] = (gj < N) ? ((const float4*)g_K)[gj * 32 + c4]
                                         : make_float4(0.f, 0.f, 0.f, 0.f);
        }
        // attention weights for this tile
#pragma unroll
        for (int l = 0; l < 4; l++) {
            int e  = t + l * 256;            // 0..1023
            int r  = e >> 6, jj = e & 63;
            int gi = i0 + r, gj = j0 + jj;
            float w = 0.f;
            if (gi < N && gj < N && A[(size_t)gi * N + gj])
                w = __expf(fabsf(pm[r] + qm[r] * g_k2[gj]) - mm[r]) * lm[r];
            wsh[r * JT + jj] = w;
        }
        __syncthreads();
#pragma unroll 4
        for (int jj = 0; jj < JT; jj++) {
            float4 kv = Ksh[jj * 32 + cg];
            float w0 = wsh[(rg * 2) * JT + jj];
            float w1 = wsh[(rg * 2 + 1) * JT + jj];
            acc0.x += w0 * kv.x; acc0.y += w0 * kv.y; acc0.z += w0 * kv.z; acc0.w += w0 * kv.w;
            acc1.x += w1 * kv.x; acc1.y += w1 * kv.y; acc1.z += w1 * kv.z; acc1.w += w1 * kv.w;
        }
        __syncthreads();
    }
    int r0 = i0 + rg * 2;
    if (r0 < N)     ((float4*)H)[(size_t)r0 * 32 + cg]       = acc0;
    if (r0 + 1 < N) ((float4*)H)[(size_t)(r0 + 1) * 32 + cg] = acc1;
}

// ---------------- launch ----------------------------------------------------
extern "C" void kernel_launch(void* const* d_in, const int* in_sizes, int n_in,
                              void* d_out, int out_size) {
    (void)in_sizes; (void)n_in; (void)out_size;
    const float* X    = (const float*)d_in[0];
    const int*   A    = (const int*)d_in[1];
    const float* U    = (const float*)d_in[2];
    const float* W    = (const float*)d_in[3];
    const float* a1   = (const float*)d_in[4];
    const float* a2   = (const float*)d_in[5];
    const float* lmbd = (const float*)d_in[6];
    float* H = (float*)d_out;

    gemm_k   <<<dim3(2, (N + 31) / 32), 256>>>(X, W);
    k1k2_kernel<<<(N + 7) / 8, 256>>>(a1, a2);
    colpart  <<<dim3((N + 255) / 256, NCH), 256>>>(U);
    colreduce<<<(N + 255) / 256, 256>>>(lmbd);
    pq_kernel<<<N, 256>>>(U);
    stats_kernel<<<N, 256>>>(A);
    attn_h   <<<(N + RPB - 1) / RPB, 256>>>(A, H);
}

// round 3
// speedup vs baseline: 1.0027x; 1.0021x over previous
#include <cuda_runtime.h>
#include <math.h>

#define N    2708
#define INC  1433
#define OC   128
#define NCH  32
#define RC   85    // ceil(N/NCH)
#define RPB  16
#define JT   64

// ---------------- scratch (static device memory, no runtime alloc) ----------
__device__ float g_K[N * OC];
__device__ float g_k1[N], g_k2[N];
__device__ float g_part1[NCH * N], g_part2[NCH * N];
__device__ float g_s1[N], g_s2[N];
__device__ float g_p[N], g_q[N];
__device__ float g_m[N], g_linv[N];

// ---------------- K = X @ W^T  (BM=32, BN=64, BK=32, 256 thr) ---------------
__global__ void gemm_k(const float* __restrict__ X, const float* __restrict__ W) {
    const int BM = 32, BN = 64, BK = 32;
    __shared__ float Xs[BM][BK + 1];
    __shared__ float Ws[BN][BK + 1];
    int i0 = blockIdx.y * BM;
    int c0 = blockIdx.x * BN;
    int t  = threadIdx.x;
    int tr = t >> 4;   // 0..15 -> rows 2*tr, 2*tr+1
    int tc = t & 15;   // 0..15 -> cols 4*tc..4*tc+3
    float acc[2][4] = {};
    for (int kt = 0; kt < INC; kt += BK) {
#pragma unroll
        for (int l = 0; l < 4; l++) {
            int e = t + l * 256;
            int r = e >> 5, kk = e & 31;
            int gi = i0 + r, gk = kt + kk;
            Xs[r][kk] = (gi < N && gk < INC) ? X[gi * INC + gk] : 0.f;
        }
#pragma unroll
        for (int l = 0; l < 8; l++) {
            int e = t + l * 256;
            int c = e >> 5, kk = e & 31;
            int gk = kt + kk;
            Ws[c][kk] = (gk < INC) ? W[(c0 + c) * INC + gk] : 0.f;
        }
        __syncthreads();
#pragma unroll
        for (int kk = 0; kk < BK; kk++) {
            float a0 = Xs[2 * tr][kk], a1 = Xs[2 * tr + 1][kk];
#pragma unroll
            for (int j = 0; j < 4; j++) {
                float b = Ws[4 * tc + j][kk];
                acc[0][j] += a0 * b;
                acc[1][j] += a1 * b;
            }
        }
        __syncthreads();
    }
#pragma unroll
    for (int r = 0; r < 2; r++) {
        int gi = i0 + 2 * tr + r;
        if (gi < N) {
#pragma unroll
            for (int j = 0; j < 4; j++)
                g_K[gi * OC + c0 + 4 * tc + j] = acc[r][j];
        }
    }
}

// ---------------- k1 = K a1^T, k2 = K a2^T (one warp per row) ---------------
__global__ void k1k2_kernel(const float* __restrict__ a1, const float* __restrict__ a2) {
    int w = threadIdx.x >> 5;
    int lane = threadIdx.x & 31;
    int i = blockIdx.x * 8 + w;
    if (i >= N) return;
    float d1 = 0.f, d2 = 0.f;
#pragma unroll
    for (int u = 0; u < 4; u++) {
        int c = lane + 32 * u;
        float kv = g_K[i * OC + c];
        d1 += kv * a1[c];
        d2 += kv * a2[c];
    }
#pragma unroll
    for (int off = 16; off; off >>= 1) {
        d1 += __shfl_down_sync(0xffffffffu, d1, off);
        d2 += __shfl_down_sync(0xffffffffu, d2, off);
    }
    if (lane == 0) { g_k1[i] = d1; g_k2[i] = d2; }
}

// ---------------- column reductions: t1 = U^T k1, t2 = U^T 1 (partials) -----
__global__ void colpart(const float* __restrict__ U) {
    int j  = blockIdx.x * 256 + threadIdx.x;
    int ch = blockIdx.y;
    if (j >= N) return;
    int ib = ch * RC;
    int ie = min(N, ib + RC);
    float a = 0.f, b = 0.f;
    for (int i = ib; i < ie; i++) {
        float u = U[i * N + j];
        a += u * g_k1[i];
        b += u;
    }
    g_part1[ch * N + j] = a;
    g_part2[ch * N + j] = b;
}

// ---------------- s = lmbd * t  (fixed-order chunk reduce) ------------------
__global__ void colreduce(const float* __restrict__ lmbd) {
    int j = blockIdx.x * 256 + threadIdx.x;
    if (j >= N) return;
    float a = 0.f, b = 0.f;
#pragma unroll
    for (int c = 0; c < NCH; c++) {
        a += g_part1[c * N + j];
        b += g_part2[c * N + j];
    }
    float l = lmbd[j];
    g_s1[j] = l * a;
    g_s2[j] = l * b;
}

// ---------------- p = U s1, q = U s2 (one block per row) --------------------
__global__ void pq_kernel(const float* __restrict__ U) {
    __shared__ float r1[256], r2[256];
    int i = blockIdx.x;
    int t = threadIdx.x;
    float a = 0.f, b = 0.f;
    for (int j = t; j < N; j += 256) {
        float u = U[i * N + j];
        a += u * g_s1[j];
        b += u * g_s2[j];
    }
    r1[t] = a; r2[t] = b;
    __syncthreads();
    for (int s = 128; s; s >>= 1) {
        if (t < s) { r1[t] += r1[t + s]; r2[t] += r2[t + s]; }
        __syncthreads();
    }
    if (t == 0) { g_p[i] = r1[0]; g_q[i] = r2[0]; }
}

// ---------------- per-row masked softmax stats: m_i, 1/l_i ------------------
__global__ void stats_kernel(const int* __restrict__ A) {
    __shared__ float red[256];
    int i = blockIdx.x, t = threadIdx.x;
    float pi = g_p[i], qi = g_q[i];
    const int* Arow = A + (size_t)i * N;
    float mx = -INFINITY;
    for (int j = t; j < N; j += 256)
        if (Arow[j]) mx = fmaxf(mx, fabsf(pi + qi * g_k2[j]));
    red[t] = mx;
    __syncthreads();
    for (int s = 128; s; s >>= 1) {
        if (t < s) red[t] = fmaxf(red[t], red[t + s]);
        __syncthreads();
    }
    float m = red[0];
    __syncthreads();
    float sum = 0.f;
    for (int j = t; j < N; j += 256)
        if (Arow[j]) sum += __expf(fabsf(pi + qi * g_k2[j]) - m);
    red[t] = sum;
    __syncthreads();
    for (int s = 128; s; s >>= 1) {
        if (t < s) red[t] += red[t + s];
        __syncthreads();
    }
    if (t == 0) { g_m[i] = m; g_linv[i] = 1.f / red[0]; }
}

// ---------------- H = alpha @ K, fused (16 rows/block, K staged in smem) ----
__global__ void attn_h(const int* __restrict__ A, float* __restrict__ H) {
    __shared__ float4 Ksh[JT * 32];            // 64 j-rows x 128 cols = 32KB
    __shared__ float  wsh[RPB * JT];           // 16 rows x 64 j        = 4KB
    __shared__ float  pm[RPB], qm[RPB], mm[RPB], lm[RPB];
    int i0 = blockIdx.x * RPB;
    int t  = threadIdx.x;
    if (t < RPB) {
        int gi = i0 + t;
        if (gi < N) { pm[t] = g_p[gi]; qm[t] = g_q[gi]; mm[t] = g_m[gi]; lm[t] = g_linv[gi]; }
        else        { pm[t] = 0.f; qm[t] = 0.f; mm[t] = 0.f; lm[t] = 0.f; }
    }
    int cg = t & 31;   // cols 4*cg..4*cg+3 (float4)
    int rg = t >> 5;   // rows 2*rg, 2*rg+1
    float4 acc0 = make_float4(0.f, 0.f, 0.f, 0.f);
    float4 acc1 = make_float4(0.f, 0.f, 0.f, 0.f);
    __syncthreads();
    for (int j0 = 0; j0 < N; j0 += JT) {
        // stage K tile (coalesced float4)
#pragma unroll
        for (int l = 0; l < 8; l++) {
            int e  = t + l * 256;            // float4 index 0..2047
            int jj = e >> 5, c4 = e & 31;
            int gj = j0 + jj;
            Ksh[jj * 32 + c4] = (gj < N) ? ((const float4*)g_K)[gj * 32 + c4]
                                         : make_float4(0.f, 0.f, 0.f, 0.f);
        }
        // attention weights for this tile
#pragma unroll
        for (int l = 0; l < 4; l++) {
            int e  = t + l * 256;            // 0..1023
            int r  = e >> 6, jj = e & 63;
            int gi = i0 + r, gj = j0 + jj;
            float w = 0.f;
            if (gi < N && gj < N && A[(size_t)gi * N + gj])
                w = __expf(fabsf(pm[r] + qm[r] * g_k2[gj]) - mm[r]) * lm[r];
            wsh[r * JT + jj] = w;
        }
        __syncthreads();
#pragma unroll 4
        for (int jj = 0; jj < JT; jj++) {
            float4 kv = Ksh[jj * 32 + cg];
            float w0 = wsh[(rg * 2) * JT + jj];
            float w1 = wsh[(rg * 2 + 1) * JT + jj];
            acc0.x += w0 * kv.x; acc0.y += w0 * kv.y; acc0.z += w0 * kv.z; acc0.w += w0 * kv.w;
            acc1.x += w1 * kv.x; acc1.y += w1 * kv.y; acc1.z += w1 * kv.z; acc1.w += w1 * kv.w;
        }
        __syncthreads();
    }
    int r0 = i0 + rg * 2;
    if (r0 < N)     ((float4*)H)[(size_t)r0 * 32 + cg]       = acc0;
    if (r0 + 1 < N) ((float4*)H)[(size_t)(r0 + 1) * 32 + cg] = acc1;
}

// ---------------- launch ----------------------------------------------------
extern "C" void kernel_launch(void* const* d_in, const int* in_sizes, int n_in,
                              void* d_out, int out_size) {
    (void)in_sizes; (void)n_in; (void)out_size;
    const float* X    = (const float*)d_in[0];
    const int*   A    = (const int*)d_in[1];
    const float* U    = (const float*)d_in[2];
    const float* W    = (const float*)d_in[3];
    const float* a1   = (const float*)d_in[4];
    const float* a2   = (const float*)d_in[5];
    const float* lmbd = (const float*)d_in[6];
    float* H = (float*)d_out;

    gemm_k   <<<dim3(2, (N + 31) / 32), 256>>>(X, W);
    k1k2_kernel<<<(N + 7) / 8, 256>>>(a1, a2);
    colpart  <<<dim3((N + 255) / 256, NCH), 256>>>(U);
    colreduce<<<(N + 255) / 256, 256>>>(lmbd);
    pq_kernel<<<N, 256>>>(U);
    stats_kernel<<<N, 256>>>(A);
    attn_h   <<<(N + RPB - 1) / RPB, 256>>>(A, H);
}